// round 2
// baseline (speedup 1.0000x reference)
#include <cuda_runtime.h>
#include <math.h>

#define P 7
#define C 512
#define H 38
#define W 38
#define NROI 128

__global__ void roipool_kernel(const float* __restrict__ x,
                               const float* __restrict__ rois,
                               float* __restrict__ out,
                               int total) {
    int idx = blockIdx.x * blockDim.x + threadIdx.x;
    if (idx >= total) return;

    // out layout: [n, c, ph, pw], pw fastest -> coalesced STG
    int pw = idx % P;
    int t  = idx / P;
    int ph = t % P;
    t /= P;
    int c  = t % C;
    int n  = t / C;

    // rois[n] = {y1, x1, y2, x2} in image coords
    const float4 r = __ldg(reinterpret_cast<const float4*>(rois) + n);
    int y1 = (int)floorf(r.x * 0.0625f);
    int x1 = (int)floorf(r.y * 0.0625f);
    int y2 = (int)floorf(r.z * 0.0625f);
    int x2 = (int)floorf(r.w * 0.0625f);

    int sh = y2 - y1 + 1;
    int sw = x2 - x1 + 1;

    // AdaptiveMaxPool bin: [lo + i*s/P, lo + ceil((i+1)*s/P))
    int hs = y1 + (ph * sh) / P;
    int he = y1 + ((ph + 1) * sh + P - 1) / P;
    int ws = x1 + (pw * sw) / P;
    int we = x1 + ((pw + 1) * sw + P - 1) / P;

    const float* __restrict__ xc = x + (long)c * (H * W);

    float m = -INFINITY;
    #pragma unroll 1
    for (int h = hs; h < he; ++h) {
        const float* __restrict__ row = xc + h * W;
        #pragma unroll 1
        for (int w = ws; w < we; ++w) {
            m = fmaxf(m, __ldg(row + w));
        }
    }
    out[idx] = m;
}

extern "C" void kernel_launch(void* const* d_in, const int* in_sizes, int n_in,
                              void* d_out, int out_size) {
    const float* x    = (const float*)d_in[0];   // [1, 512, 38, 38]
    const float* rois = (const float*)d_in[1];   // [128, 4]
    float* out        = (float*)d_out;           // [128, 512, 7, 7]

    int total = NROI * C * P * P;                // 3,211,264
    int threads = 256;
    int blocks = (total + threads - 1) / threads;
    roipool_kernel<<<blocks, threads>>>(x, rois, out, total);
}

// round 3
// speedup vs baseline: 1.0010x; 1.0010x over previous
#include <cuda_runtime.h>
#include <math.h>

#define P 7
#define C 512
#define H 38
#define W 38
#define NROI 128

__global__ void roipool_kernel(const float* __restrict__ x,
                               const float* __restrict__ rois,
                               float* __restrict__ out,
                               int total) {
    int idx = blockIdx.x * blockDim.x + threadIdx.x;
    if (idx >= total) return;

    // out layout: [n, c, ph, pw], pw fastest -> coalesced STG
    int pw = idx % P;
    int t  = idx / P;
    int ph = t % P;
    t /= P;
    int c  = t % C;
    int n  = t / C;

    // rois[n] = {y1, x1, y2, x2} in image coords
    const float4 r = __ldg(reinterpret_cast<const float4*>(rois) + n);
    int y1 = (int)floorf(r.x * 0.0625f);
    int x1 = (int)floorf(r.y * 0.0625f);
    int y2 = (int)floorf(r.z * 0.0625f);
    int x2 = (int)floorf(r.w * 0.0625f);

    int sh = y2 - y1 + 1;
    int sw = x2 - x1 + 1;

    // AdaptiveMaxPool bin: [lo + i*s/P, lo + ceil((i+1)*s/P))
    int hs = y1 + (ph * sh) / P;
    int he = y1 + ((ph + 1) * sh + P - 1) / P;
    int ws = x1 + (pw * sw) / P;
    int we = x1 + ((pw + 1) * sw + P - 1) / P;

    const float* __restrict__ xc = x + (long)c * (H * W);

    float m = -INFINITY;
    #pragma unroll 1
    for (int h = hs; h < he; ++h) {
        const float* __restrict__ row = xc + h * W;
        #pragma unroll 1
        for (int w = ws; w < we; ++w) {
            m = fmaxf(m, __ldg(row + w));
        }
    }
    out[idx] = m;
}

extern "C" void kernel_launch(void* const* d_in, const int* in_sizes, int n_in,
                              void* d_out, int out_size) {
    const float* x    = (const float*)d_in[0];   // [1, 512, 38, 38]
    const float* rois = (const float*)d_in[1];   // [128, 4]
    float* out        = (float*)d_out;           // [128, 512, 7, 7]

    int total = NROI * C * P * P;                // 3,211,264
    int threads = 256;
    int blocks = (total + threads - 1) / threads;
    roipool_kernel<<<blocks, threads>>>(x, rois, out, total);
}

// round 4
// speedup vs baseline: 1.2526x; 1.2513x over previous
#include <cuda_runtime.h>
#include <math.h>

#define P    7
#define C    512
#define H    38
#define W    38
#define NROI 128
#define HW   (H * W)          // 1444
#define CZ   8                // threadIdx.z extent
#define CPT  4                // channels per thread
#define CB   (CZ * CPT)       // 32 channels per block

__global__ __launch_bounds__(P * P * CZ)
void roipool_kernel(const float* __restrict__ x,
                    const float* __restrict__ rois,
                    float* __restrict__ out) {
    const int pw = threadIdx.x;                 // 0..6
    const int ph = threadIdx.y;                 // 0..6
    const int cz = threadIdx.z;                 // 0..7
    const int n  = blockIdx.y;                  // roi
    const int c0 = blockIdx.x * CB + cz;        // first of 4 channels

    // ---- per-block bin tables (one RoI per block) ----
    __shared__ int s_hs[P], s_he[P], s_ws[P], s_we[P];
    if (threadIdx.y == 0 && threadIdx.z == 0) {
        const float4 r = __ldg(reinterpret_cast<const float4*>(rois) + n);
        int y1 = (int)floorf(r.x * 0.0625f);
        int x1 = (int)floorf(r.y * 0.0625f);
        int sh = (int)floorf(r.z * 0.0625f) - y1 + 1;
        int sw = (int)floorf(r.w * 0.0625f) - x1 + 1;
        int i = pw;                              // 0..6
        s_hs[i] = y1 + (i * sh) / P;
        s_he[i] = y1 + ((i + 1) * sh + P - 1) / P;
        s_ws[i] = x1 + (i * sw) / P;
        s_we[i] = x1 + ((i + 1) * sw + P - 1) / P;
    }
    __syncthreads();

    const int hs = s_hs[ph];
    const int he = s_he[ph];
    const int ws = s_ws[pw];
    const int we = s_we[pw];

    const float* __restrict__ base = x + c0 * HW;

    float m0 = -INFINITY, m1 = -INFINITY, m2 = -INFINITY, m3 = -INFINITY;

    const float* __restrict__ row = base + hs * W;
    #pragma unroll 1
    for (int h = hs; h < he; ++h, row += W) {
        #pragma unroll 1
        for (int w = ws; w < we; ++w) {
            // 4 channel planes via constant immediate offsets off one address
            m0 = fmaxf(m0, __ldg(row + w));
            m1 = fmaxf(m1, __ldg(row + w +  8 * HW));
            m2 = fmaxf(m2, __ldg(row + w + 16 * HW));
            m3 = fmaxf(m3, __ldg(row + w + 24 * HW));
        }
    }

    // out layout [n, c, ph, pw]; warp lanes (pw fastest) -> coalesced stores
    float* o = out + ((long)n * C + c0) * (P * P) + ph * P + pw;
    o[0]            = m0;
    o[ 8 * P * P]   = m1;
    o[16 * P * P]   = m2;
    o[24 * P * P]   = m3;
}

extern "C" void kernel_launch(void* const* d_in, const int* in_sizes, int n_in,
                              void* d_out, int out_size) {
    const float* x    = (const float*)d_in[0];   // [1, 512, 38, 38]
    const float* rois = (const float*)d_in[1];   // [128, 4]
    float* out        = (float*)d_out;           // [128, 512, 7, 7]

    dim3 block(P, P, CZ);                        // 392 threads
    dim3 grid(C / CB, NROI);                     // (16, 128)
    roipool_kernel<<<grid, block>>>(x, rois, out);
}

// round 5
// speedup vs baseline: 1.2542x; 1.0013x over previous
#include <cuda_runtime.h>
#include <math.h>

#define P    7
#define C    512
#define H    38
#define W    38
#define NROI 128
#define HW   (H * W)          // 1444
#define CZ   8                // threadIdx.z extent
#define CPT  4                // channels per thread
#define CB   (CZ * CPT)       // 32 channels per block

__global__ __launch_bounds__(P * P * CZ)
void roipool_kernel(const float* __restrict__ x,
                    const float* __restrict__ rois,
                    float* __restrict__ out) {
    const int pw = threadIdx.x;                 // 0..6
    const int ph = threadIdx.y;                 // 0..6
    const int cz = threadIdx.z;                 // 0..7
    const int n  = blockIdx.y;                  // roi
    const int c0 = blockIdx.x * CB + cz;        // first of 4 channels

    // ---- per-block bin tables (one RoI per block) ----
    __shared__ int s_hs[P], s_he[P], s_ws[P], s_we[P];
    if (threadIdx.y == 0 && threadIdx.z == 0) {
        const float4 r = __ldg(reinterpret_cast<const float4*>(rois) + n);
        int y1 = (int)floorf(r.x * 0.0625f);
        int x1 = (int)floorf(r.y * 0.0625f);
        int sh = (int)floorf(r.z * 0.0625f) - y1 + 1;
        int sw = (int)floorf(r.w * 0.0625f) - x1 + 1;
        int i = pw;                              // 0..6
        s_hs[i] = y1 + (i * sh) / P;
        s_he[i] = y1 + ((i + 1) * sh + P - 1) / P;
        s_ws[i] = x1 + (i * sw) / P;
        s_we[i] = x1 + ((i + 1) * sw + P - 1) / P;
    }
    __syncthreads();

    const int hs = s_hs[ph];
    const int he = s_he[ph];
    const int ws = s_ws[pw];
    const int we = s_we[pw];

    const float* __restrict__ base = x + c0 * HW;

    float m0 = -INFINITY, m1 = -INFINITY, m2 = -INFINITY, m3 = -INFINITY;

    const float* __restrict__ row = base + hs * W;
    #pragma unroll 1
    for (int h = hs; h < he; ++h, row += W) {
        #pragma unroll 1
        for (int w = ws; w < we; ++w) {
            // 4 channel planes via constant immediate offsets off one address
            m0 = fmaxf(m0, __ldg(row + w));
            m1 = fmaxf(m1, __ldg(row + w +  8 * HW));
            m2 = fmaxf(m2, __ldg(row + w + 16 * HW));
            m3 = fmaxf(m3, __ldg(row + w + 24 * HW));
        }
    }

    // out layout [n, c, ph, pw]; warp lanes (pw fastest) -> coalesced stores
    float* o = out + ((long)n * C + c0) * (P * P) + ph * P + pw;
    o[0]            = m0;
    o[ 8 * P * P]   = m1;
    o[16 * P * P]   = m2;
    o[24 * P * P]   = m3;
}

extern "C" void kernel_launch(void* const* d_in, const int* in_sizes, int n_in,
                              void* d_out, int out_size) {
    const float* x    = (const float*)d_in[0];   // [1, 512, 38, 38]
    const float* rois = (const float*)d_in[1];   // [128, 4]
    float* out        = (float*)d_out;           // [128, 512, 7, 7]

    dim3 block(P, P, CZ);                        // 392 threads
    dim3 grid(C / CB, NROI);                     // (16, 128)
    roipool_kernel<<<grid, block>>>(x, rois, out);
}